// round 1
// baseline (speedup 1.0000x reference)
#include <cuda_runtime.h>
#include <cstdint>

// Problem constants
#define B_ROWS 2000000u
#define F_COLS 21u
#define N_ELEM (B_ROWS * F_COLS)          // 42,000,000 (divisible by 4)
#define N_VEC  (N_ELEM / 4u)              // 10,500,000
#define NUM_CLASSES 7

#define NBLOCKS 1480
#define NTHREADS 256

// Fixed per-block partials -> fully deterministic two-stage reduction, no atomics.
__device__ double g_part_wd[NBLOCKS];
__device__ double g_part_pen[NBLOCKS];

__global__ __launch_bounds__(NTHREADS)
void wmse_reduce_kernel(const float* __restrict__ x,
                        const int*   __restrict__ t,
                        const float* __restrict__ w)
{
    __shared__ float sw[NUM_CLASSES];
    __shared__ float s_wd[NTHREADS / 32];
    __shared__ float s_pen[NTHREADS / 32];

    if (threadIdx.x < NUM_CLASSES) sw[threadIdx.x] = w[threadIdx.x];
    __syncthreads();

    float accw = 0.0f;   // sum of w_i * diff^2
    float accp = 0.0f;   // sum of range penalties (col 1 only)

    const unsigned stride = gridDim.x * blockDim.x;
    for (unsigned v = blockIdx.x * blockDim.x + threadIdx.x; v < N_VEC; v += stride) {
        const unsigned base = v * 4u;

        const float4 xv = __ldg(reinterpret_cast<const float4*>(x) + v);
        const int4   tv = __ldg(reinterpret_cast<const int4*>(t) + v);

        // Row / column of the first lane (compiler turns /21 into magic mul)
        const unsigned r = base / F_COLS;
        const unsigned c = base - r * F_COLS;

        // Class weight for this row; second row's weight only if this vec4 crosses
        // a row boundary. The class element lives in the same lines we're streaming
        // -> L1 hit almost always.
        const int   cls0 = __ldg(t + r * F_COLS + 2u);
        const float w0   = sw[cls0 / 100 - 1];
        float       w1   = w0;
        if (c + 3u >= F_COLS) {
            const int cls1 = __ldg(t + (r + 1u) * F_COLS + 2u);
            w1 = sw[cls1 / 100 - 1];
        }

        const float xe[4] = { xv.x, xv.y, xv.z, xv.w };
        const int   te[4] = { tv.x, tv.y, tv.z, tv.w };

        #pragma unroll
        for (int k = 0; k < 4; ++k) {
            const unsigned ck   = c + (unsigned)k;
            const bool     next = (ck >= F_COLS);
            const float    wk   = next ? w1 : w0;
            const unsigned col  = next ? (ck - F_COLS) : ck;

            const float d = xe[k] - (float)te[k];
            accw = fmaf(wk * d, d, accw);

            if (col == 1u) {
                const float vv = (float)te[k];
                if (vv > 1000.0f) {
                    const float e = vv - 1000.0f;
                    accp = fmaf(e, e, accp);
                } else if (vv < 0.0f) {
                    accp = fmaf(vv, vv, accp);
                }
            }
        }
    }

    // Warp reduce (float; per-thread partials are only ~111 terms -> safe)
    #pragma unroll
    for (int o = 16; o > 0; o >>= 1) {
        accw += __shfl_xor_sync(0xffffffffu, accw, o);
        accp += __shfl_xor_sync(0xffffffffu, accp, o);
    }
    const int warp = threadIdx.x >> 5;
    const int lane = threadIdx.x & 31;
    if (lane == 0) { s_wd[warp] = accw; s_pen[warp] = accp; }
    __syncthreads();

    if (threadIdx.x == 0) {
        double dw = 0.0, dp = 0.0;
        #pragma unroll
        for (int i = 0; i < NTHREADS / 32; ++i) { dw += (double)s_wd[i]; dp += (double)s_pen[i]; }
        g_part_wd[blockIdx.x]  = dw;
        g_part_pen[blockIdx.x] = dp;
    }
}

__global__ __launch_bounds__(256)
void wmse_final_kernel(float* __restrict__ out)
{
    __shared__ double s_wd[8];
    __shared__ double s_pen[8];

    double dw = 0.0, dp = 0.0;
    for (int i = threadIdx.x; i < NBLOCKS; i += blockDim.x) {
        dw += g_part_wd[i];
        dp += g_part_pen[i];
    }
    #pragma unroll
    for (int o = 16; o > 0; o >>= 1) {
        dw += __shfl_xor_sync(0xffffffffu, dw, o);
        dp += __shfl_xor_sync(0xffffffffu, dp, o);
    }
    const int warp = threadIdx.x >> 5;
    const int lane = threadIdx.x & 31;
    if (lane == 0) { s_wd[warp] = dw; s_pen[warp] = dp; }
    __syncthreads();
    if (threadIdx.x == 0) {
        double tw = 0.0, tp = 0.0;
        #pragma unroll
        for (int i = 0; i < 8; ++i) { tw += s_wd[i]; tp += s_pen[i]; }
        const double mean_wd = tw / (double)((unsigned long long)B_ROWS * F_COLS);
        out[0] = (float)(mean_wd + tp);
    }
}

extern "C" void kernel_launch(void* const* d_in, const int* in_sizes, int n_in,
                              void* d_out, int out_size)
{
    // metadata order: inputs (f32 [B,F]), targets (i32 [B,F]), weights (f32 [7]).
    // Defensive: find the 7-element tensor as weights; the two big ones keep order.
    const float* x = nullptr;
    const int*   t = nullptr;
    const float* w = nullptr;
    int big_seen = 0;
    for (int i = 0; i < n_in; ++i) {
        if (in_sizes[i] == NUM_CLASSES) {
            w = (const float*)d_in[i];
        } else {
            if (big_seen == 0) x = (const float*)d_in[i];
            else               t = (const int*)d_in[i];
            big_seen++;
        }
    }

    wmse_reduce_kernel<<<NBLOCKS, NTHREADS>>>(x, t, w);
    wmse_final_kernel<<<1, 256>>>((float*)d_out);
}

// round 2
// speedup vs baseline: 1.0994x; 1.0994x over previous
#include <cuda_runtime.h>
#include <cstdint>

// Problem constants
#define B_ROWS 2000000u
#define F_COLS 21u
#define N_ELEM (B_ROWS * F_COLS)          // 42,000,000 (divisible by 4)
#define N_VEC  (N_ELEM / 4u)              // 10,500,000
#define NUM_CLASSES 7

#define NBLOCKS 1480
#define NTHREADS 256

// Fixed per-block partials -> deterministic reduction order, no alloc, no 2nd kernel.
__device__ double        g_part_wd[NBLOCKS];
__device__ double        g_part_pen[NBLOCKS];
__device__ unsigned int  g_done_count = 0;   // reset by the last block each launch

__device__ __forceinline__ void accum_vec4(
    const float4 xv, const int4 tv, unsigned base,
    const float* __restrict__ t_as_f_unused, const int* __restrict__ t,
    const float* sw, float& accw, float& accp)
{
    const unsigned r = base / F_COLS;                 // magic-mul, no real divide
    const unsigned c = base - r * F_COLS;

    const int   cls0 = __ldg(t + r * F_COLS + 2u);    // same line as the stream -> L1 hit
    const float w0   = sw[cls0 / 100 - 1];
    float       w1   = w0;
    if (c + 3u >= F_COLS) {
        const int cls1 = __ldg(t + (r + 1u) * F_COLS + 2u);
        w1 = sw[cls1 / 100 - 1];
    }

    const float xe[4] = { xv.x, xv.y, xv.z, xv.w };
    const int   te[4] = { tv.x, tv.y, tv.z, tv.w };

    #pragma unroll
    for (int k = 0; k < 4; ++k) {
        const unsigned ck   = c + (unsigned)k;
        const bool     next = (ck >= F_COLS);
        const float    wk   = next ? w1 : w0;
        const unsigned col  = next ? (ck - F_COLS) : ck;

        const float d = xe[k] - (float)te[k];
        accw = fmaf(wk * d, d, accw);

        if (col == 1u) {
            const float vv = (float)te[k];
            if (vv > 1000.0f) {
                const float e = vv - 1000.0f;
                accp = fmaf(e, e, accp);
            } else if (vv < 0.0f) {
                accp = fmaf(vv, vv, accp);
            }
        }
    }
}

__global__ __launch_bounds__(NTHREADS)
void wmse_fused_kernel(const float* __restrict__ x,
                       const int*   __restrict__ t,
                       const float* __restrict__ w,
                       float*       __restrict__ out)
{
    __shared__ float  sw[NUM_CLASSES];
    __shared__ float  s_wd[NTHREADS / 32];
    __shared__ float  s_pen[NTHREADS / 32];
    __shared__ bool   s_is_last;

    if (threadIdx.x < NUM_CLASSES) sw[threadIdx.x] = w[threadIdx.x];
    __syncthreads();

    float accw = 0.0f;
    float accp = 0.0f;

    const unsigned stride  = gridDim.x * blockDim.x;
    const unsigned stride2 = stride * 2u;
    unsigned v = blockIdx.x * blockDim.x + threadIdx.x;

    // Unroll x2 over two grid-stride streams: front-batch 4-6 LDG.128s per iter.
    for (; v + stride < N_VEC; v += stride2) {
        const unsigned va = v;
        const unsigned vb = v + stride;

        const float4 xa = __ldg(reinterpret_cast<const float4*>(x) + va);
        const int4   ta = __ldg(reinterpret_cast<const int4*>(t) + va);
        const float4 xb = __ldg(reinterpret_cast<const float4*>(x) + vb);
        const int4   tb = __ldg(reinterpret_cast<const int4*>(t) + vb);

        accum_vec4(xa, ta, va * 4u, nullptr, t, sw, accw, accp);
        accum_vec4(xb, tb, vb * 4u, nullptr, t, sw, accw, accp);
    }
    if (v < N_VEC) {
        const float4 xa = __ldg(reinterpret_cast<const float4*>(x) + v);
        const int4   ta = __ldg(reinterpret_cast<const int4*>(t) + v);
        accum_vec4(xa, ta, v * 4u, nullptr, t, sw, accw, accp);
    }

    // Warp reduce
    #pragma unroll
    for (int o = 16; o > 0; o >>= 1) {
        accw += __shfl_xor_sync(0xffffffffu, accw, o);
        accp += __shfl_xor_sync(0xffffffffu, accp, o);
    }
    const int warp = threadIdx.x >> 5;
    const int lane = threadIdx.x & 31;
    if (lane == 0) { s_wd[warp] = accw; s_pen[warp] = accp; }
    __syncthreads();

    if (threadIdx.x == 0) {
        double dw = 0.0, dp = 0.0;
        #pragma unroll
        for (int i = 0; i < NTHREADS / 32; ++i) { dw += (double)s_wd[i]; dp += (double)s_pen[i]; }
        g_part_wd[blockIdx.x]  = dw;
        g_part_pen[blockIdx.x] = dp;

        __threadfence();  // make partials visible before signaling done
        const unsigned prev = atomicAdd(&g_done_count, 1u);
        s_is_last = (prev == (unsigned)(gridDim.x - 1));
    }
    __syncthreads();

    // Last block to finish folds the partials (fixed order -> deterministic).
    if (s_is_last) {
        __threadfence();  // acquire all other blocks' partial writes
        double dw = 0.0, dp = 0.0;
        for (int i = threadIdx.x; i < NBLOCKS; i += NTHREADS) {
            dw += g_part_wd[i];
            dp += g_part_pen[i];
        }
        #pragma unroll
        for (int o = 16; o > 0; o >>= 1) {
            dw += __shfl_xor_sync(0xffffffffu, dw, o);
            dp += __shfl_xor_sync(0xffffffffu, dp, o);
        }
        __shared__ double f_wd[NTHREADS / 32];
        __shared__ double f_pen[NTHREADS / 32];
        if (lane == 0) { f_wd[warp] = dw; f_pen[warp] = dp; }
        __syncthreads();
        if (threadIdx.x == 0) {
            double tw = 0.0, tp = 0.0;
            #pragma unroll
            for (int i = 0; i < NTHREADS / 32; ++i) { tw += f_wd[i]; tp += f_pen[i]; }
            const double mean_wd = tw / (double)((unsigned long long)B_ROWS * F_COLS);
            out[0] = (float)(mean_wd + tp);
            g_done_count = 0;   // reset for the next graph replay
        }
    }
}

extern "C" void kernel_launch(void* const* d_in, const int* in_sizes, int n_in,
                              void* d_out, int out_size)
{
    // metadata order: inputs (f32 [B,F]), targets (i32 [B,F]), weights (f32 [7]).
    const float* x = nullptr;
    const int*   t = nullptr;
    const float* w = nullptr;
    int big_seen = 0;
    for (int i = 0; i < n_in; ++i) {
        if (in_sizes[i] == NUM_CLASSES) {
            w = (const float*)d_in[i];
        } else {
            if (big_seen == 0) x = (const float*)d_in[i];
            else               t = (const int*)d_in[i];
            big_seen++;
        }
    }

    wmse_fused_kernel<<<NBLOCKS, NTHREADS>>>(x, t, w, (float*)d_out);
}

// round 3
// speedup vs baseline: 1.1653x; 1.0599x over previous
#include <cuda_runtime.h>
#include <cstdint>

#define B_ROWS 2000000u
#define F_COLS 21u
#define N_ELEM (B_ROWS * F_COLS)          // 42,000,000
#define N_VEC  (N_ELEM / 4u)              // 10,500,000
#define NUM_CLASSES 7

// grid·threads·4 must be divisible by 21 so each thread's column phase is
// loop-invariant. 882 = 21*42, and 882 <= 148 SMs * 6 blocks => one wave.
#define NBLOCKS 882
#define NTHREADS 256
#define STRIDE_VEC (NBLOCKS * NTHREADS)   // 225,792 vec4s; *4 = 903,168 ≡ 0 (mod 21)

__device__ double        g_part_wd[NBLOCKS];
__device__ double        g_part_pen[NBLOCKS];
__device__ unsigned int  g_done_count = 0;

__device__ __forceinline__ void proc_vec4(
    const float4 xv, const int4 tv, unsigned v, unsigned c,
    bool boundary, unsigned s, int kp,
    const int* __restrict__ t, const float* sw,
    float& accw, float& accp)
{
    const unsigned cbase = v * 4u - c;            // element index of row start
    const int   cls0 = __ldg(t + cbase + 2u);
    const float w0   = sw[(unsigned)cls0 / 100u - 1u];

    const float d0 = xv.x - (float)tv.x;
    const float d1 = xv.y - (float)tv.y;
    const float d2 = xv.z - (float)tv.z;
    const float d3 = xv.w - (float)tv.w;
    const float q0 = d0 * d0, q1 = d1 * d1, q2 = d2 * d2, q3 = d3 * d3;
    const float q  = (q0 + q1) + (q2 + q3);
    accw = fmaf(w0, q, accw);

    if (boundary) {                               // loop-invariant predicate
        const int   cls1 = __ldg(t + cbase + 23u);   // next row's class
        const float w1   = sw[(unsigned)cls1 / 100u - 1u];
        float qhi = q3;                           // k >= s belong to next row
        if (s <= 2u) qhi += q2;
        if (s <= 1u) qhi += q1;
        accw = fmaf(w1 - w0, qhi, accw);
    }
    if (kp >= 0) {                                // loop-invariant predicate
        const int tp = (kp == 0) ? tv.x : (kp == 1) ? tv.y : (kp == 2) ? tv.z : tv.w;
        const float vv = (float)tp;
        if (vv > 1000.0f) {
            const float e = vv - 1000.0f;
            accp = fmaf(e, e, accp);
        } else if (vv < 0.0f) {
            accp = fmaf(vv, vv, accp);
        }
    }
}

__global__ __launch_bounds__(NTHREADS, 6)
void wmse_fused_kernel(const float* __restrict__ x,
                       const int*   __restrict__ t,
                       const float* __restrict__ w,
                       float*       __restrict__ out)
{
    __shared__ float sw[NUM_CLASSES];
    __shared__ float s_wd[NTHREADS / 32];
    __shared__ float s_pen[NTHREADS / 32];
    __shared__ bool  s_is_last;

    if (threadIdx.x < NUM_CLASSES) sw[threadIdx.x] = w[threadIdx.x];
    __syncthreads();

    const unsigned v0   = blockIdx.x * NTHREADS + threadIdx.x;
    const unsigned base = v0 * 4u;
    const unsigned r0   = base / F_COLS;            // magic-mul once
    const unsigned c    = base - r0 * F_COLS;       // loop-invariant phase

    const bool     boundary = (c >= 18u);
    const unsigned s        = F_COLS - c;           // first k of next row (1..3 if boundary)
    int kp = -1;                                    // penalty lane (col==1), at most one
    if      (c <= 1u)  kp = 1 - (int)c;             // ck == 1
    else if (c >= 19u) kp = 22 - (int)c;            // ck == 22 (next row, col 1)

    float accw = 0.0f, accp = 0.0f;

    unsigned v = v0;
    // unroll x2, loads front-batched
    for (; v + STRIDE_VEC < N_VEC; v += 2u * STRIDE_VEC) {
        const unsigned va = v, vb = v + STRIDE_VEC;
        const float4 xa = __ldg(reinterpret_cast<const float4*>(x) + va);
        const int4   ta = __ldg(reinterpret_cast<const int4*>(t) + va);
        const float4 xb = __ldg(reinterpret_cast<const float4*>(x) + vb);
        const int4   tb = __ldg(reinterpret_cast<const int4*>(t) + vb);
        proc_vec4(xa, ta, va, c, boundary, s, kp, t, sw, accw, accp);
        proc_vec4(xb, tb, vb, c, boundary, s, kp, t, sw, accw, accp);
    }
    if (v < N_VEC) {
        const float4 xa = __ldg(reinterpret_cast<const float4*>(x) + v);
        const int4   ta = __ldg(reinterpret_cast<const int4*>(t) + v);
        proc_vec4(xa, ta, v, c, boundary, s, kp, t, sw, accw, accp);
    }

    // warp reduce
    #pragma unroll
    for (int o = 16; o > 0; o >>= 1) {
        accw += __shfl_xor_sync(0xffffffffu, accw, o);
        accp += __shfl_xor_sync(0xffffffffu, accp, o);
    }
    const int warp = threadIdx.x >> 5;
    const int lane = threadIdx.x & 31;
    if (lane == 0) { s_wd[warp] = accw; s_pen[warp] = accp; }
    __syncthreads();

    if (threadIdx.x == 0) {
        double dw = 0.0, dp = 0.0;
        #pragma unroll
        for (int i = 0; i < NTHREADS / 32; ++i) { dw += (double)s_wd[i]; dp += (double)s_pen[i]; }
        g_part_wd[blockIdx.x]  = dw;
        g_part_pen[blockIdx.x] = dp;
        __threadfence();
        const unsigned prev = atomicAdd(&g_done_count, 1u);
        s_is_last = (prev == (unsigned)(gridDim.x - 1));
    }
    __syncthreads();

    if (s_is_last) {
        __threadfence();
        double dw = 0.0, dp = 0.0;
        for (int i = threadIdx.x; i < NBLOCKS; i += NTHREADS) {
            dw += g_part_wd[i];
            dp += g_part_pen[i];
        }
        #pragma unroll
        for (int o = 16; o > 0; o >>= 1) {
            dw += __shfl_xor_sync(0xffffffffu, dw, o);
            dp += __shfl_xor_sync(0xffffffffu, dp, o);
        }
        __shared__ double f_wd[NTHREADS / 32];
        __shared__ double f_pen[NTHREADS / 32];
        if (lane == 0) { f_wd[warp] = dw; f_pen[warp] = dp; }
        __syncthreads();
        if (threadIdx.x == 0) {
            double tw = 0.0, tp = 0.0;
            #pragma unroll
            for (int i = 0; i < NTHREADS / 32; ++i) { tw += f_wd[i]; tp += f_pen[i]; }
            const double mean_wd = tw / (double)((unsigned long long)B_ROWS * F_COLS);
            out[0] = (float)(mean_wd + tp);
            g_done_count = 0;   // reset for next graph replay
        }
    }
}

extern "C" void kernel_launch(void* const* d_in, const int* in_sizes, int n_in,
                              void* d_out, int out_size)
{
    const float* x = nullptr;
    const int*   t = nullptr;
    const float* w = nullptr;
    int big_seen = 0;
    for (int i = 0; i < n_in; ++i) {
        if (in_sizes[i] == NUM_CLASSES) {
            w = (const float*)d_in[i];
        } else {
            if (big_seen == 0) x = (const float*)d_in[i];
            else               t = (const int*)d_in[i];
            big_seen++;
        }
    }
    wmse_fused_kernel<<<NBLOCKS, NTHREADS>>>(x, t, w, (float*)d_out);
}